// round 12
// baseline (speedup 1.0000x reference)
#include <cuda_runtime.h>
#include <cstdint>

// Fixed problem shapes
constexpr int B_ = 32, N_ = 128, K_ = 16, F_ = 256, D_ = 256;
constexpr int NF_TILES = 512;   // 128-row nbr tiles
constexpr int AF_TILES = 32;

// scratch (device globals)
__device__ float g_af[4096 * 256];     // af results (4 MB)
__device__ float g_ctx[4096 * 256];    // pre-LN context (4 MB)
__device__ float g_wnp[256 * 256];     // tf32 + pair-packed Wn
__device__ float g_wap[256 * 256];     // tf32 + pair-packed Wa

// ---------------- GEMM core config (256 thr, 128x128 tile, 3-stage) ----------------
constexpr int GT     = 256;      // 8 warps: rb 0..3 (32 rows), cb 0..1 (64 cols)
constexpr int CH     = 32;       // K chunk
constexpr int NCH    = 8;
constexpr int BSTR   = 40;       // B stage row stride (pair-packed); 40%32==8 -> conflict-free LDS.64
constexpr int B_OFF  = 4096;     // B region offset inside stage (A: 128x32 swizzled)
constexpr int STG_FL = B_OFF + 128 * BSTR;   // 9216 floats per stage
constexpr int SMEM_FL = 3 * STG_FL;          // 27648 floats = 110592 B -> 2 CTAs/SM

// epilogue smem overlay (aliases stage 0; written after mainloop)
constexpr int E_AFB = 0;             // 8 atoms x 128 cols (af + ba)
constexpr int E_BN  = E_AFB + 1024;  // 128
constexpr int E_WAL = E_BN + 128;    // 64
constexpr int E_SMK = E_WAL + 64;    // 128
constexpr int E_AMK = E_SMK + 128;   // 128
constexpr int E_SC  = E_AMK + 128;   // 8 atoms x 16 k x 2 heads
constexpr int E_AW  = E_SC + 256;

__device__ __forceinline__ uint32_t s2u(const void* p) {
    return static_cast<uint32_t>(__cvta_generic_to_shared(p));
}
__device__ __forceinline__ void cp16(uint32_t dst, const void* src) {
    asm volatile("cp.async.cg.shared.global [%0], [%1], 16;\n" :: "r"(dst), "l"(src));
}
__device__ __forceinline__ float tf32f(float x) {
    float y;
    asm("cvt.rna.tf32.f32 %0, %1;" : "=f"(y) : "f"(x));
    return y;
}
__device__ __forceinline__ uint32_t tf32u(float x) { return __float_as_uint(tf32f(x)); }

__device__ __forceinline__ void mma_tf32(float c[4], uint32_t a0, uint32_t a1,
                                         uint32_t a2, uint32_t a3,
                                         uint32_t b0, uint32_t b1) {
    asm volatile(
        "mma.sync.aligned.m16n8k8.row.col.f32.tf32.tf32.f32 "
        "{%0,%1,%2,%3},{%4,%5,%6,%7},{%8,%9},{%0,%1,%2,%3};"
        : "+f"(c[0]), "+f"(c[1]), "+f"(c[2]), "+f"(c[3])
        : "r"(a0), "r"(a1), "r"(a2), "r"(a3), "r"(b0), "r"(b1));
}

// issue one chunk into stage c%3: A raw fp32 (XOR-swizzled), B pair-packed (stride 40)
__device__ __forceinline__ void issue_chunk(float* s, const float* __restrict__ Ag,
                                            const float* __restrict__ Wp,
                                            int row0, int c, int tid) {
    const int stg = (c % 3) * STG_FL;
#pragma unroll
    for (int i = 0; i < 4; i++) {
        int id  = tid + i * GT;          // 0..1023
        int row = id >> 3, c4 = id & 7;
        int sw  = (c4 ^ (row & 7)) << 2; // 16B-granule swizzle (A only)
        cp16(s2u(s + stg + row * CH + sw),
             Ag + (size_t)(row0 + row) * F_ + c * CH + c4 * 4);
        cp16(s2u(s + stg + B_OFF + row * BSTR + c4 * 4),
             Wp + (size_t)row * F_ + c * CH + c4 * 4);
    }
}

// GEMM mainloop: acc[2][8][4]; warp tile rows rb*32, cols cb*64 (of 128)
__device__ __forceinline__ void run_gemm(float* s, const float* __restrict__ Ag,
                                         const float* __restrict__ Wp,
                                         int row0, int tid, float acc[2][8][4]) {
    const int lane = tid & 31;
    const int w    = tid >> 5;
    const int l4   = lane & 3;
    const int lr   = lane >> 2;
    const int rb   = w >> 1;      // 0..3
    const int cb   = w & 1;       // 0..1

    issue_chunk(s, Ag, Wp, row0, 0, tid);
    asm volatile("cp.async.commit_group;\n");
    issue_chunk(s, Ag, Wp, row0, 1, tid);
    asm volatile("cp.async.commit_group;\n");

#pragma unroll
    for (int c = 0; c < NCH; c++) {
        if (c == NCH - 1) asm volatile("cp.async.wait_group 0;\n");
        else              asm volatile("cp.async.wait_group 1;\n");
        __syncthreads();   // chunk c visible; stage (c+2)%3 readers (iter c-1) done
        if (c + 2 < NCH) {
            issue_chunk(s, Ag, Wp, row0, c + 2, tid);
            asm volatile("cp.async.commit_group;\n");
        }

        const float* sa  = s + (c % 3) * STG_FL;
        const float* sbb = sa + B_OFF;
#pragma unroll
        for (int g = 0; g < 4; g++) {
            const int u    = (2 * g) ^ lr;
            const int off0 = (u << 2) + l4;          // A: k = g*8 + l4
            const int off1 = ((u ^ 1) << 2) + l4;    // A: k = g*8 + 4 + l4
            uint32_t a[2][4];
#pragma unroll
            for (int rf = 0; rf < 2; rf++) {
                const float* ap = sa + (rb * 32 + rf * 16 + lr) * CH;
                a[rf][0] = tf32u(ap[off0]);
                a[rf][1] = tf32u(ap[8 * CH + off0]);
                a[rf][2] = tf32u(ap[off1]);
                a[rf][3] = tf32u(ap[8 * CH + off1]);
            }
            // B pair-packed: one LDS.64 per fragment, conflict-free (stride 40)
            const float* bp = sbb + (cb * 64 + lr) * BSTR + g * 8 + 2 * l4;
#pragma unroll
            for (int j = 0; j < 8; j++) {
                float2 b = *(const float2*)(bp + j * 8 * BSTR);
                uint32_t b0 = __float_as_uint(b.x);
                uint32_t b1 = __float_as_uint(b.y);
                mma_tf32(acc[0][j], a[0][0], a[0][1], a[0][2], a[0][3], b0, b1);
                mma_tf32(acc[1][j], a[1][0], a[1][1], a[1][2], a[1][3], b0, b1);
            }
        }
    }
}

// ---------------- W repack: tf32 + (k, k+4) pair interleave ----------------
__global__ void __launch_bounds__(256)
wpack_kernel(const float* __restrict__ Wn, const float* __restrict__ Wa)
{
    int gid = blockIdx.x * 256 + threadIdx.x;   // 0..4095: (wsel, d, c)
    int wsel = gid >> 11;
    int rem  = gid & 2047;
    int d = rem >> 3, c = rem & 7;
    const float* src = (wsel ? Wa : Wn) + (size_t)d * F_ + c * CH;
    float* dst = (wsel ? g_wap : g_wnp) + (size_t)d * F_ + c * CH;
#pragma unroll
    for (int g = 0; g < 4; g++)
#pragma unroll
        for (int l4 = 0; l4 < 4; l4++) {
            dst[g * 8 + 2 * l4]     = tf32f(src[g * 8 + l4]);
            dst[g * 8 + 2 * l4 + 1] = tf32f(src[g * 8 + l4 + 4]);
        }
}

// ---------------- af GEMM ----------------
__global__ void __launch_bounds__(GT, 2)
af_gemm_kernel(const float* __restrict__ atom)
{
    extern __shared__ float s[];
    const int tid = threadIdx.x;
    const int tile = blockIdx.x >> 1;
    const int hc   = blockIdx.x & 1;
    const int row0 = tile * 128;

    float acc[2][8][4];
#pragma unroll
    for (int rf = 0; rf < 2; rf++)
#pragma unroll
        for (int j = 0; j < 8; j++)
#pragma unroll
            for (int q = 0; q < 4; q++) acc[rf][j][q] = 0.f;

    run_gemm(s, atom, g_wap + (size_t)(hc * 128) * F_, row0, tid, acc);

    const int lane = tid & 31, w = tid >> 5;
    const int l4 = lane & 3, lr = lane >> 2;
    const int rb = w >> 1, cb = w & 1;
#pragma unroll
    for (int rf = 0; rf < 2; rf++) {
        int r0 = row0 + rb * 32 + rf * 16 + lr;
#pragma unroll
        for (int j = 0; j < 8; j++) {
            int col = hc * 128 + cb * 64 + j * 8 + 2 * l4;
            *(float2*)(g_af + (size_t)r0 * D_ + col)
                = make_float2(acc[rf][j][0], acc[rf][j][1]);
            *(float2*)(g_af + (size_t)(r0 + 8) * D_ + col)
                = make_float2(acc[rf][j][2], acc[rf][j][3]);
        }
    }
}

// ---------------- fused nf GEMM + score/softmax/ctx ----------------
__global__ void __launch_bounds__(GT, 2)
fused_kernel(const float* __restrict__ nbr,
             const float* __restrict__ smask,
             const float* __restrict__ amask,
             const float* __restrict__ ba,
             const float* __restrict__ bn,
             const float* __restrict__ wal,
             const float* __restrict__ bal)
{
    extern __shared__ float s[];
    const int tid  = threadIdx.x;
    const int tile = blockIdx.x >> 1;     // 0..511 : 8 atoms each
    const int hc   = blockIdx.x & 1;      // column half (heads hc*2, hc*2+1)
    const int row0 = tile * 128;
    const int atom0 = tile * 8;

    float acc[2][8][4];
#pragma unroll
    for (int rf = 0; rf < 2; rf++)
#pragma unroll
        for (int j = 0; j < 8; j++)
#pragma unroll
            for (int q = 0; q < 4; q++) acc[rf][j][q] = 0.f;

    run_gemm(s, nbr, g_wnp + (size_t)(hc * 128) * F_, row0, tid, acc);
    // past final barrier: stage-0 region safe to overlay (chunk 7 reads stage 1)

    const int lane = tid & 31, w = tid >> 5;
    const int l4 = lane & 3, lr = lane >> 2;
    const int rb = w >> 1, cb = w & 1;

    // ---- phase 0: loads ----
    {
        int a  = tid >> 5;            // atom 0..7
        int c4 = tid & 31;            // float4 col
        float4 va = *(const float4*)(g_af + (size_t)(atom0 + a) * D_ + hc * 128 + c4 * 4);
        float4 vb = *(const float4*)(ba + hc * 128 + c4 * 4);
        *(float4*)(s + E_AFB + a * 128 + c4 * 4)
            = make_float4(va.x + vb.x, va.y + vb.y, va.z + vb.z, va.w + vb.w);
        if (tid < 32)
            ((float4*)(s + E_BN))[tid] = ((const float4*)(bn + hc * 128))[tid];
        else if (tid < 48)
            ((float4*)(s + E_WAL))[tid - 32] = ((const float4*)wal)[tid - 32];
        else if (tid >= 64 && tid < 96)
            ((float4*)(s + E_SMK))[tid - 64] = ((const float4*)(smask + atom0 * K_))[tid - 64];
        else if (tid >= 96 && tid < 128)
            ((float4*)(s + E_AMK))[tid - 96] = ((const float4*)(amask + atom0 * K_))[tid - 96];
    }
    const float bal_s = bal[0];
    __syncthreads();

    // ---- phase 1: score partials (atom = rb*2+rf, head-local = cb) ----
#pragma unroll
    for (int rf = 0; rf < 2; rf++) {
        const int a = rb * 2 + rf;
        float s1 = 0.f, s2 = 0.f;
#pragma unroll
        for (int j = 0; j < 8; j++) {
            int c0 = cb * 64 + j * 8 + 2 * l4;
            float af0 = s[E_AFB + a * 128 + c0], af1 = s[E_AFB + a * 128 + c0 + 1];
            float b0  = s[E_BN + c0],            b1  = s[E_BN + c0 + 1];
            float w0  = s[E_WAL + ((j * 8 + 2 * l4) & 63)];
            float w1  = s[E_WAL + ((j * 8 + 2 * l4 + 1) & 63)];
            float t;
            t = af0 + acc[rf][j][0] + b0; t = (t > 0.f) ? t : 0.2f * t; s1 = fmaf(t, w0, s1);
            t = af1 + acc[rf][j][1] + b1; t = (t > 0.f) ? t : 0.2f * t; s1 = fmaf(t, w1, s1);
            t = af0 + acc[rf][j][2] + b0; t = (t > 0.f) ? t : 0.2f * t; s2 = fmaf(t, w0, s2);
            t = af1 + acc[rf][j][3] + b1; t = (t > 0.f) ? t : 0.2f * t; s2 = fmaf(t, w1, s2);
        }
        s1 += __shfl_xor_sync(0xffffffffu, s1, 1);
        s1 += __shfl_xor_sync(0xffffffffu, s1, 2);
        s2 += __shfl_xor_sync(0xffffffffu, s2, 1);
        s2 += __shfl_xor_sync(0xffffffffu, s2, 2);
        if (l4 == 0) {
            s[E_SC + a * 32 + lr * 2 + cb]       = s1;   // k = lr
            s[E_SC + a * 32 + (lr + 8) * 2 + cb] = s2;   // k = lr+8
        }
    }
    __syncthreads();

    // ---- phase 2: softmax over k (16 threads: (atom, local head)) ----
    if (tid < 16) {
        const int a = tid >> 1, hh = tid & 1;
        float sc[K_], mx = -3.4e38f;
#pragma unroll
        for (int k = 0; k < K_; k++) {
            sc[k] = s[E_SC + a * 32 + k * 2 + hh] + bal_s + s[E_SMK + a * 16 + k];
            mx = fmaxf(mx, sc[k]);
        }
        float ssum = 0.f;
#pragma unroll
        for (int k = 0; k < K_; k++) { sc[k] = __expf(sc[k] - mx); ssum += sc[k]; }
        float inv = 1.f / ssum;
#pragma unroll
        for (int k = 0; k < K_; k++)
            s[E_AW + a * 32 + k * 2 + hh] = sc[k] * inv * s[E_AMK + a * 16 + k];
    }
    __syncthreads();

    // ---- phase 3: ctx -> g_ctx ----
#pragma unroll
    for (int rf = 0; rf < 2; rf++) {
        const int a = rb * 2 + rf;
        const float aw1 = s[E_AW + a * 32 + lr * 2 + cb];
        const float aw2 = s[E_AW + a * 32 + (lr + 8) * 2 + cb];
#pragma unroll
        for (int j = 0; j < 8; j++) {
            int c0 = cb * 64 + j * 8 + 2 * l4;
            float b0 = s[E_BN + c0], b1 = s[E_BN + c0 + 1];
            float c0v = aw1 * (acc[rf][j][0] + b0) + aw2 * (acc[rf][j][2] + b0);
            float c1v = aw1 * (acc[rf][j][1] + b1) + aw2 * (acc[rf][j][3] + b1);
#pragma unroll
            for (int off = 4; off <= 16; off <<= 1) {
                c0v += __shfl_xor_sync(0xffffffffu, c0v, off);
                c1v += __shfl_xor_sync(0xffffffffu, c1v, off);
            }
            if (lr == 0)
                *(float2*)(g_ctx + (size_t)(atom0 + a) * D_ + hc * 128 + c0)
                    = make_float2(c0v, c1v);
        }
    }
}

// ---------------- LayerNorm (warp per 2 rows, ILP) ----------------
__global__ void __launch_bounds__(256)
ln_kernel(const float* __restrict__ gam, const float* __restrict__ bet,
          float* __restrict__ out)
{
    const int lane = threadIdx.x & 31;
    const int w    = threadIdx.x >> 5;
    const int r0   = blockIdx.x * 16 + w * 2;     // two rows per warp

    const float* sA = g_ctx + (size_t)r0 * D_;
    const float* sB = g_ctx + (size_t)(r0 + 1) * D_;
    float4 a0 = ((const float4*)sA)[lane];
    float4 a1 = ((const float4*)sA)[lane + 32];
    float4 b0 = ((const float4*)sB)[lane];
    float4 b1 = ((const float4*)sB)[lane + 32];

    float sa1 = a0.x + a0.y + a0.z + a0.w + a1.x + a1.y + a1.z + a1.w;
    float sa2 = a0.x*a0.x + a0.y*a0.y + a0.z*a0.z + a0.w*a0.w
              + a1.x*a1.x + a1.y*a1.y + a1.z*a1.z + a1.w*a1.w;
    float sb1 = b0.x + b0.y + b0.z + b0.w + b1.x + b1.y + b1.z + b1.w;
    float sb2 = b0.x*b0.x + b0.y*b0.y + b0.z*b0.z + b0.w*b0.w
              + b1.x*b1.x + b1.y*b1.y + b1.z*b1.z + b1.w*b1.w;
#pragma unroll
    for (int off = 16; off; off >>= 1) {
        sa1 += __shfl_xor_sync(0xffffffffu, sa1, off);
        sa2 += __shfl_xor_sync(0xffffffffu, sa2, off);
        sb1 += __shfl_xor_sync(0xffffffffu, sb1, off);
        sb2 += __shfl_xor_sync(0xffffffffu, sb2, off);
    }
    float muA  = sa1 * (1.f / 256.f);
    float rsA  = rsqrtf(sa2 * (1.f / 256.f) - muA * muA + 1e-5f);
    float muB  = sb1 * (1.f / 256.f);
    float rsB  = rsqrtf(sb2 * (1.f / 256.f) - muB * muB + 1e-5f);

    float4 g0 = ((const float4*)gam)[lane];
    float4 g1 = ((const float4*)gam)[lane + 32];
    float4 e0 = ((const float4*)bet)[lane];
    float4 e1 = ((const float4*)bet)[lane + 32];
    float4 o;
    o.x = (a0.x - muA) * rsA * g0.x + e0.x;
    o.y = (a0.y - muA) * rsA * g0.y + e0.y;
    o.z = (a0.z - muA) * rsA * g0.z + e0.z;
    o.w = (a0.w - muA) * rsA * g0.w + e0.w;
    ((float4*)(out + (size_t)r0 * D_))[lane] = o;
    o.x = (a1.x - muA) * rsA * g1.x + e1.x;
    o.y = (a1.y - muA) * rsA * g1.y + e1.y;
    o.z = (a1.z - muA) * rsA * g1.z + e1.z;
    o.w = (a1.w - muA) * rsA * g1.w + e1.w;
    ((float4*)(out + (size_t)r0 * D_))[lane + 32] = o;
    o.x = (b0.x - muB) * rsB * g0.x + e0.x;
    o.y = (b0.y - muB) * rsB * g0.y + e0.y;
    o.z = (b0.z - muB) * rsB * g0.z + e0.z;
    o.w = (b0.w - muB) * rsB * g0.w + e0.w;
    ((float4*)(out + (size_t)(r0 + 1) * D_))[lane] = o;
    o.x = (b1.x - muB) * rsB * g1.x + e1.x;
    o.y = (b1.y - muB) * rsB * g1.y + e1.y;
    o.z = (b1.z - muB) * rsB * g1.z + e1.z;
    o.w = (b1.w - muB) * rsB * g1.w + e1.w;
    ((float4*)(out + (size_t)(r0 + 1) * D_))[lane + 32] = o;
}

extern "C" void kernel_launch(void* const* d_in, const int* in_sizes, int n_in,
                              void* d_out, int out_size)
{
    const float* atom_feat = (const float*)d_in[0];
    const float* nbr_feat  = (const float*)d_in[1];
    const float* smask     = (const float*)d_in[2];
    const float* amask     = (const float*)d_in[3];
    const float* Wa        = (const float*)d_in[4];
    const float* ba        = (const float*)d_in[5];
    const float* Wn        = (const float*)d_in[6];
    const float* bn        = (const float*)d_in[7];
    const float* wal       = (const float*)d_in[8];
    const float* bal       = (const float*)d_in[9];
    const float* gam       = (const float*)d_in[10];
    const float* bet       = (const float*)d_in[11];
    float* out = (float*)d_out;

    cudaFuncSetAttribute(af_gemm_kernel,
                         cudaFuncAttributeMaxDynamicSharedMemorySize,
                         SMEM_FL * (int)sizeof(float));
    cudaFuncSetAttribute(fused_kernel,
                         cudaFuncAttributeMaxDynamicSharedMemorySize,
                         SMEM_FL * (int)sizeof(float));

    wpack_kernel<<<16, 256>>>(Wn, Wa);
    af_gemm_kernel<<<AF_TILES * 2, GT, SMEM_FL * sizeof(float)>>>(atom_feat);
    fused_kernel<<<NF_TILES * 2, GT, SMEM_FL * sizeof(float)>>>(
        nbr_feat, smask, amask, ba, bn, wal, bal);
    ln_kernel<<<4096 / 16, 256>>>(gam, bet, out);
}

// round 13
// speedup vs baseline: 1.2166x; 1.2166x over previous
#include <cuda_runtime.h>
#include <cstdint>

// Fixed problem shapes
constexpr int B_ = 32, N_ = 128, K_ = 16, F_ = 256, D_ = 256;
constexpr int NF_TILES = 512;   // 128-row nbr tiles
constexpr int AF_TILES = 32;

// scratch (device globals)
__device__ float g_af[4096 * 256];     // af results (4 MB)
__device__ float g_ctx[4096 * 256];    // pre-LN context (4 MB)
__device__ float g_wnp[256 * 256];     // tf32 + (k,k+4) pair-packed Wn
__device__ float g_wap[256 * 256];     // tf32 + (k,k+4) pair-packed Wa

// ---------------- GEMM core config (256 thr, 128x128 tile, 3-stage) ----------------
constexpr int GT     = 256;      // 8 warps: rb 0..3 (32 rows), cb 0..1 (64 cols)
constexpr int CH     = 32;       // K chunk
constexpr int NCH    = 8;
constexpr int BSTR   = 40;       // B stage row stride; 40%32==8 -> conflict-free LDS.64
constexpr int B_OFF  = 4096;     // B region offset inside stage (A: 128x32 swizzled)
constexpr int STG_FL = B_OFF + 128 * BSTR;   // 9216 floats per stage
constexpr int SMEM_FL = 3 * STG_FL;          // 27648 floats = 110592 B -> 2 CTAs/SM

// epilogue smem overlay (aliases stage 0; written after mainloop)
constexpr int E_AFB = 0;             // 8 atoms x 128 cols (af + ba)
constexpr int E_BN  = E_AFB + 1024;  // 128
constexpr int E_WAL = E_BN + 128;    // 64
constexpr int E_SMK = E_WAL + 64;    // 128
constexpr int E_AMK = E_SMK + 128;   // 128
constexpr int E_SC  = E_AMK + 128;   // 8 atoms x 16 k x 2 heads
constexpr int E_AW  = E_SC + 256;

__device__ __forceinline__ uint32_t s2u(const void* p) {
    return static_cast<uint32_t>(__cvta_generic_to_shared(p));
}
__device__ __forceinline__ void cp16(uint32_t dst, const void* src) {
    asm volatile("cp.async.cg.shared.global [%0], [%1], 16;\n" :: "r"(dst), "l"(src));
}
__device__ __forceinline__ float tf32f(float x) {
    float y;
    asm("cvt.rna.tf32.f32 %0, %1;" : "=f"(y) : "f"(x));
    return y;
}

__device__ __forceinline__ void mma_tf32(float c[4], uint32_t a0, uint32_t a1,
                                         uint32_t a2, uint32_t a3,
                                         uint32_t b0, uint32_t b1) {
    asm volatile(
        "mma.sync.aligned.m16n8k8.row.col.f32.tf32.tf32.f32 "
        "{%0,%1,%2,%3},{%4,%5,%6,%7},{%8,%9},{%0,%1,%2,%3};"
        : "+f"(c[0]), "+f"(c[1]), "+f"(c[2]), "+f"(c[3])
        : "r"(a0), "r"(a1), "r"(a2), "r"(a3), "r"(b0), "r"(b1));
}

// issue one chunk into stage c%3: A raw fp32 (XOR-swizzled), B pair-packed (stride 40)
__device__ __forceinline__ void issue_chunk(float* s, const float* __restrict__ Ag,
                                            const float* __restrict__ Wp,
                                            int row0, int c, int tid) {
    const int stg = (c % 3) * STG_FL;
#pragma unroll
    for (int i = 0; i < 4; i++) {
        int id  = tid + i * GT;          // 0..1023
        int row = id >> 3, c4 = id & 7;
        int sw  = (c4 ^ (row & 7)) << 2; // 16B-granule swizzle (A only)
        cp16(s2u(s + stg + row * CH + sw),
             Ag + (size_t)(row0 + row) * F_ + c * CH + c4 * 4);
        cp16(s2u(s + stg + B_OFF + row * BSTR + c4 * 4),
             Wp + (size_t)row * F_ + c * CH + c4 * 4);
    }
}

// GEMM mainloop: acc[2][8][4]; warp tile rows rb*32, cols cb*64 (of 128)
// A operands fed as raw fp32 bits: tf32 HMMA uses top 19 bits (RZ truncation).
__device__ __forceinline__ void run_gemm(float* s, const float* __restrict__ Ag,
                                         const float* __restrict__ Wp,
                                         int row0, int tid, float acc[2][8][4]) {
    const int lane = tid & 31;
    const int w    = tid >> 5;
    const int l4   = lane & 3;
    const int lr   = lane >> 2;
    const int rb   = w >> 1;      // 0..3
    const int cb   = w & 1;       // 0..1

    issue_chunk(s, Ag, Wp, row0, 0, tid);
    asm volatile("cp.async.commit_group;\n");
    issue_chunk(s, Ag, Wp, row0, 1, tid);
    asm volatile("cp.async.commit_group;\n");

#pragma unroll
    for (int c = 0; c < NCH; c++) {
        if (c == NCH - 1) asm volatile("cp.async.wait_group 0;\n");
        else              asm volatile("cp.async.wait_group 1;\n");
        __syncthreads();   // chunk c visible; stage (c+2)%3 readers (iter c-1) done
        if (c + 2 < NCH) {
            issue_chunk(s, Ag, Wp, row0, c + 2, tid);
            asm volatile("cp.async.commit_group;\n");
        }

        const float* sa  = s + (c % 3) * STG_FL;
        const float* sbb = sa + B_OFF;
#pragma unroll
        for (int g = 0; g < 4; g++) {
            const int u    = (2 * g) ^ lr;
            const int off0 = (u << 2) + l4;          // A: k = g*8 + l4
            const int off1 = ((u ^ 1) << 2) + l4;    // A: k = g*8 + 4 + l4
            uint32_t a[2][4];
#pragma unroll
            for (int rf = 0; rf < 2; rf++) {
                const float* ap = sa + (rb * 32 + rf * 16 + lr) * CH;
                a[rf][0] = __float_as_uint(ap[off0]);
                a[rf][1] = __float_as_uint(ap[8 * CH + off0]);
                a[rf][2] = __float_as_uint(ap[off1]);
                a[rf][3] = __float_as_uint(ap[8 * CH + off1]);
            }
            // B pair-packed: one LDS.64 per fragment, conflict-free (stride 40)
            const float* bp = sbb + (cb * 64 + lr) * BSTR + g * 8 + 2 * l4;
#pragma unroll
            for (int j = 0; j < 8; j++) {
                float2 b = *(const float2*)(bp + j * 8 * BSTR);
                uint32_t b0 = __float_as_uint(b.x);
                uint32_t b1 = __float_as_uint(b.y);
                mma_tf32(acc[0][j], a[0][0], a[0][1], a[0][2], a[0][3], b0, b1);
                mma_tf32(acc[1][j], a[1][0], a[1][1], a[1][2], a[1][3], b0, b1);
            }
        }
    }
}

// ---------------- W repack: tf32 + (k, k+4) pair interleave, vectorized ----------------
// thread per 8-float octet: 2x LDG.128 -> 8 cvt -> 2x STG.128, fully coalesced.
__global__ void __launch_bounds__(256)
wpack_kernel(const float* __restrict__ Wn, const float* __restrict__ Wa)
{
    int gid = blockIdx.x * 256 + threadIdx.x;   // 0..16383 octets
    int wsel = gid >> 13;
    int oct  = gid & 8191;                       // octet within matrix (d*32 + o)
    const float* src = (wsel ? Wa : Wn) + (size_t)oct * 8;
    float* dst = (wsel ? g_wap : g_wnp) + (size_t)oct * 8;
    float4 lo = ((const float4*)src)[0];
    float4 hi = ((const float4*)src)[1];
    float4 o0 = make_float4(tf32f(lo.x), tf32f(hi.x), tf32f(lo.y), tf32f(hi.y));
    float4 o1 = make_float4(tf32f(lo.z), tf32f(hi.z), tf32f(lo.w), tf32f(hi.w));
    ((float4*)dst)[0] = o0;
    ((float4*)dst)[1] = o1;
}

// ---------------- af GEMM ----------------
__global__ void __launch_bounds__(GT, 2)
af_gemm_kernel(const float* __restrict__ atom)
{
    extern __shared__ float s[];
    const int tid = threadIdx.x;
    const int tile = blockIdx.x >> 1;
    const int hc   = blockIdx.x & 1;
    const int row0 = tile * 128;

    float acc[2][8][4];
#pragma unroll
    for (int rf = 0; rf < 2; rf++)
#pragma unroll
        for (int j = 0; j < 8; j++)
#pragma unroll
            for (int q = 0; q < 4; q++) acc[rf][j][q] = 0.f;

    run_gemm(s, atom, g_wap + (size_t)(hc * 128) * F_, row0, tid, acc);

    const int lane = tid & 31, w = tid >> 5;
    const int l4 = lane & 3, lr = lane >> 2;
    const int rb = w >> 1, cb = w & 1;
#pragma unroll
    for (int rf = 0; rf < 2; rf++) {
        int r0 = row0 + rb * 32 + rf * 16 + lr;
#pragma unroll
        for (int j = 0; j < 8; j++) {
            int col = hc * 128 + cb * 64 + j * 8 + 2 * l4;
            *(float2*)(g_af + (size_t)r0 * D_ + col)
                = make_float2(acc[rf][j][0], acc[rf][j][1]);
            *(float2*)(g_af + (size_t)(r0 + 8) * D_ + col)
                = make_float2(acc[rf][j][2], acc[rf][j][3]);
        }
    }
}

// ---------------- fused nf GEMM + score/softmax/ctx ----------------
__global__ void __launch_bounds__(GT, 2)
fused_kernel(const float* __restrict__ nbr,
             const float* __restrict__ smask,
             const float* __restrict__ amask,
             const float* __restrict__ ba,
             const float* __restrict__ bn,
             const float* __restrict__ wal,
             const float* __restrict__ bal)
{
    extern __shared__ float s[];
    const int tid  = threadIdx.x;
    const int tile = blockIdx.x >> 1;     // 0..511 : 8 atoms each
    const int hc   = blockIdx.x & 1;      // column half (heads hc*2, hc*2+1)
    const int row0 = tile * 128;
    const int atom0 = tile * 8;

    float acc[2][8][4];
#pragma unroll
    for (int rf = 0; rf < 2; rf++)
#pragma unroll
        for (int j = 0; j < 8; j++)
#pragma unroll
            for (int q = 0; q < 4; q++) acc[rf][j][q] = 0.f;

    run_gemm(s, nbr, g_wnp + (size_t)(hc * 128) * F_, row0, tid, acc);
    // past final barrier: stage-0 region safe to overlay (chunk 7 reads stage 1)

    const int lane = tid & 31, w = tid >> 5;
    const int l4 = lane & 3, lr = lane >> 2;
    const int rb = w >> 1, cb = w & 1;

    // ---- phase 0: loads ----
    {
        int a  = tid >> 5;            // atom 0..7
        int c4 = tid & 31;            // float4 col
        float4 va = *(const float4*)(g_af + (size_t)(atom0 + a) * D_ + hc * 128 + c4 * 4);
        float4 vb = *(const float4*)(ba + hc * 128 + c4 * 4);
        *(float4*)(s + E_AFB + a * 128 + c4 * 4)
            = make_float4(va.x + vb.x, va.y + vb.y, va.z + vb.z, va.w + vb.w);
        if (tid < 32)
            ((float4*)(s + E_BN))[tid] = ((const float4*)(bn + hc * 128))[tid];
        else if (tid < 48)
            ((float4*)(s + E_WAL))[tid - 32] = ((const float4*)wal)[tid - 32];
        else if (tid >= 64 && tid < 96)
            ((float4*)(s + E_SMK))[tid - 64] = ((const float4*)(smask + atom0 * K_))[tid - 64];
        else if (tid >= 96 && tid < 128)
            ((float4*)(s + E_AMK))[tid - 96] = ((const float4*)(amask + atom0 * K_))[tid - 96];
    }
    const float bal_s = bal[0];
    __syncthreads();

    // ---- phase 1: score partials (atom = rb*2+rf, head-local = cb) ----
#pragma unroll
    for (int rf = 0; rf < 2; rf++) {
        const int a = rb * 2 + rf;
        float s1 = 0.f, s2 = 0.f;
#pragma unroll
        for (int j = 0; j < 8; j++) {
            int c0 = cb * 64 + j * 8 + 2 * l4;
            float af0 = s[E_AFB + a * 128 + c0], af1 = s[E_AFB + a * 128 + c0 + 1];
            float b0  = s[E_BN + c0],            b1  = s[E_BN + c0 + 1];
            float w0  = s[E_WAL + ((j * 8 + 2 * l4) & 63)];
            float w1  = s[E_WAL + ((j * 8 + 2 * l4 + 1) & 63)];
            float t;
            t = af0 + acc[rf][j][0] + b0; t = (t > 0.f) ? t : 0.2f * t; s1 = fmaf(t, w0, s1);
            t = af1 + acc[rf][j][1] + b1; t = (t > 0.f) ? t : 0.2f * t; s1 = fmaf(t, w1, s1);
            t = af0 + acc[rf][j][2] + b0; t = (t > 0.f) ? t : 0.2f * t; s2 = fmaf(t, w0, s2);
            t = af1 + acc[rf][j][3] + b1; t = (t > 0.f) ? t : 0.2f * t; s2 = fmaf(t, w1, s2);
        }
        s1 += __shfl_xor_sync(0xffffffffu, s1, 1);
        s1 += __shfl_xor_sync(0xffffffffu, s1, 2);
        s2 += __shfl_xor_sync(0xffffffffu, s2, 1);
        s2 += __shfl_xor_sync(0xffffffffu, s2, 2);
        if (l4 == 0) {
            s[E_SC + a * 32 + lr * 2 + cb]       = s1;   // k = lr
            s[E_SC + a * 32 + (lr + 8) * 2 + cb] = s2;   // k = lr+8
        }
    }
    __syncthreads();

    // ---- phase 2: softmax over k (16 threads: (atom, local head)) ----
    if (tid < 16) {
        const int a = tid >> 1, hh = tid & 1;
        float sc[K_], mx = -3.4e38f;
#pragma unroll
        for (int k = 0; k < K_; k++) {
            sc[k] = s[E_SC + a * 32 + k * 2 + hh] + bal_s + s[E_SMK + a * 16 + k];
            mx = fmaxf(mx, sc[k]);
        }
        float ssum = 0.f;
#pragma unroll
        for (int k = 0; k < K_; k++) { sc[k] = __expf(sc[k] - mx); ssum += sc[k]; }
        float inv = 1.f / ssum;
#pragma unroll
        for (int k = 0; k < K_; k++)
            s[E_AW + a * 32 + k * 2 + hh] = sc[k] * inv * s[E_AMK + a * 16 + k];
    }
    __syncthreads();

    // ---- phase 3: ctx -> g_ctx ----
#pragma unroll
    for (int rf = 0; rf < 2; rf++) {
        const int a = rb * 2 + rf;
        const float aw1 = s[E_AW + a * 32 + lr * 2 + cb];
        const float aw2 = s[E_AW + a * 32 + (lr + 8) * 2 + cb];
#pragma unroll
        for (int j = 0; j < 8; j++) {
            int c0 = cb * 64 + j * 8 + 2 * l4;
            float b0 = s[E_BN + c0], b1 = s[E_BN + c0 + 1];
            float c0v = aw1 * (acc[rf][j][0] + b0) + aw2 * (acc[rf][j][2] + b0);
            float c1v = aw1 * (acc[rf][j][1] + b1) + aw2 * (acc[rf][j][3] + b1);
#pragma unroll
            for (int off = 4; off <= 16; off <<= 1) {
                c0v += __shfl_xor_sync(0xffffffffu, c0v, off);
                c1v += __shfl_xor_sync(0xffffffffu, c1v, off);
            }
            if (lr == 0)
                *(float2*)(g_ctx + (size_t)(atom0 + a) * D_ + hc * 128 + c0)
                    = make_float2(c0v, c1v);
        }
    }
}

// ---------------- LayerNorm (warp per row; R11 version) ----------------
__global__ void __launch_bounds__(256)
ln_kernel(const float* __restrict__ gam, const float* __restrict__ bet,
          float* __restrict__ out)
{
    const int lane = threadIdx.x & 31;
    const int w    = threadIdx.x >> 5;
    const int row  = blockIdx.x * 8 + w;

    const float* src = g_ctx + (size_t)row * D_;
    float4 v0 = ((const float4*)src)[lane];
    float4 v1 = ((const float4*)src)[lane + 32];
    float s1 = v0.x + v0.y + v0.z + v0.w + v1.x + v1.y + v1.z + v1.w;
    float s2 = v0.x*v0.x + v0.y*v0.y + v0.z*v0.z + v0.w*v0.w
             + v1.x*v1.x + v1.y*v1.y + v1.z*v1.z + v1.w*v1.w;
#pragma unroll
    for (int off = 16; off; off >>= 1) {
        s1 += __shfl_xor_sync(0xffffffffu, s1, off);
        s2 += __shfl_xor_sync(0xffffffffu, s2, off);
    }
    float mu  = s1 * (1.f / 256.f);
    float var = s2 * (1.f / 256.f) - mu * mu;
    float rs  = rsqrtf(var + 1e-5f);

    float4 g0 = ((const float4*)gam)[lane];
    float4 g1 = ((const float4*)gam)[lane + 32];
    float4 b0 = ((const float4*)bet)[lane];
    float4 b1 = ((const float4*)bet)[lane + 32];
    float4 o0, o1;
    o0.x = (v0.x - mu) * rs * g0.x + b0.x;
    o0.y = (v0.y - mu) * rs * g0.y + b0.y;
    o0.z = (v0.z - mu) * rs * g0.z + b0.z;
    o0.w = (v0.w - mu) * rs * g0.w + b0.w;
    o1.x = (v1.x - mu) * rs * g1.x + b1.x;
    o1.y = (v1.y - mu) * rs * g1.y + b1.y;
    o1.z = (v1.z - mu) * rs * g1.z + b1.z;
    o1.w = (v1.w - mu) * rs * g1.w + b1.w;
    ((float4*)(out + (size_t)row * D_))[lane]      = o0;
    ((float4*)(out + (size_t)row * D_))[lane + 32] = o1;
}

extern "C" void kernel_launch(void* const* d_in, const int* in_sizes, int n_in,
                              void* d_out, int out_size)
{
    const float* atom_feat = (const float*)d_in[0];
    const float* nbr_feat  = (const float*)d_in[1];
    const float* smask     = (const float*)d_in[2];
    const float* amask     = (const float*)d_in[3];
    const float* Wa        = (const float*)d_in[4];
    const float* ba        = (const float*)d_in[5];
    const float* Wn        = (const float*)d_in[6];
    const float* bn        = (const float*)d_in[7];
    const float* wal       = (const float*)d_in[8];
    const float* bal       = (const float*)d_in[9];
    const float* gam       = (const float*)d_in[10];
    const float* bet       = (const float*)d_in[11];
    float* out = (float*)d_out;

    cudaFuncSetAttribute(af_gemm_kernel,
                         cudaFuncAttributeMaxDynamicSharedMemorySize,
                         SMEM_FL * (int)sizeof(float));
    cudaFuncSetAttribute(fused_kernel,
                         cudaFuncAttributeMaxDynamicSharedMemorySize,
                         SMEM_FL * (int)sizeof(float));

    wpack_kernel<<<64, 256>>>(Wn, Wa);
    af_gemm_kernel<<<AF_TILES * 2, GT, SMEM_FL * sizeof(float)>>>(atom_feat);
    fused_kernel<<<NF_TILES * 2, GT, SMEM_FL * sizeof(float)>>>(
        nbr_feat, smask, amask, ba, bn, wal, bal);
    ln_kernel<<<4096 / 8, 256>>>(gam, bet, out);
}